// round 3
// baseline (speedup 1.0000x reference)
#include <cuda_runtime.h>
#include <cuda_bf16.h>

static constexpr int Bc      = 256;   // batches
static constexpr int Nn      = 512;   // nodes
static constexpr int SPLIT   = 4;     // row-chunks per batch
static constexpr int ROWS    = Nn / SPLIT;   // 128 rows per block
static constexpr int THREADS = 256;
static constexpr int WARPS   = THREADS / 32;

// Deterministic partial sums: [batch][chunk]  (no FP atomics anywhere)
__device__ float g_partial[Bc * SPLIT];

__global__ __launch_bounds__(THREADS)
void gcn_main(const float* __restrict__ x,     // [B, N, 2]
              const float* __restrict__ adj,   // [B, N, N]
              const float* __restrict__ W1,    // [2, 4] row-major
              const float* __restrict__ b1,    // [4]
              const float* __restrict__ W2)    // [4, 1]
{
    const int blk   = blockIdx.x;
    const int b     = blk >> 2;        // / SPLIT
    const int chunk = blk & (SPLIT - 1);
    const int tid   = threadIdx.x;
    const int lane  = tid & 31;
    const int warp  = tid >> 5;

    // Tiny MLP params -> shared (read only by lane 0 of each warp)
    __shared__ float sW[16];           // [0..7]=W1, [8..11]=b1, [12..15]=W2
    __shared__ float warp_sums[WARPS];
    if (tid < 8)  sW[tid]      = W1[tid];
    if (tid < 4)  sW[8 + tid]  = b1[tid];
    if (tid < 4)  sW[12 + tid] = W2[tid];

    // Preload this lane's fixed x-slice into registers.
    // Lane l owns m = it*128 + 4*l + k  (it=0..3, k=0..3): 16 (x0,x1) pairs.
    float rx0[16], rx1[16];
    {
        const float* xb = x + (size_t)b * Nn * 2;
        #pragma unroll
        for (int it = 0; it < 4; ++it) {
            const int m = it * 128 + lane * 4;
            #pragma unroll
            for (int k = 0; k < 4; ++k) {
                const float2 v = *(const float2*)(xb + (size_t)(m + k) * 2);
                rx0[it * 4 + k] = v.x;
                rx1[it * 4 + k] = v.y;
            }
        }
    }
    __syncthreads();

    float wsum = 0.0f;   // per-(warp,lane0) accumulator of node propensities

    const int n_base = chunk * ROWS;
    for (int r = warp; r < ROWS; r += WARPS) {
        const int n = n_base + r;
        const float4* __restrict__ arow =
            (const float4*)(adj + ((size_t)b * Nn + n) * Nn);

        float s0 = 0.0f, s1 = 0.0f;
        #pragma unroll
        for (int it = 0; it < 4; ++it) {
            // streaming load: adj has zero reuse -> evict-first
            const float4 a = __ldcs(arow + it * 32 + lane);
            s0 = fmaf(a.x, rx0[it * 4 + 0], s0);
            s1 = fmaf(a.x, rx1[it * 4 + 0], s1);
            s0 = fmaf(a.y, rx0[it * 4 + 1], s0);
            s1 = fmaf(a.y, rx1[it * 4 + 1], s1);
            s0 = fmaf(a.z, rx0[it * 4 + 2], s0);
            s1 = fmaf(a.z, rx1[it * 4 + 2], s1);
            s0 = fmaf(a.w, rx0[it * 4 + 3], s0);
            s1 = fmaf(a.w, rx1[it * 4 + 3], s1);
        }

        // warp reduction of (s0, s1)
        #pragma unroll
        for (int off = 16; off > 0; off >>= 1) {
            s0 += __shfl_xor_sync(0xFFFFFFFFu, s0, off);
            s1 += __shfl_xor_sync(0xFFFFFFFFu, s1, off);
        }

        if (lane == 0) {
            float p = 0.0f;
            #pragma unroll
            for (int j = 0; j < 4; ++j) {
                const float h = fmaf(s0, sW[j], fmaf(s1, sW[4 + j], sW[8 + j]));
                p = fmaf(fmaxf(h, 0.0f), sW[12 + j], p);
            }
            wsum += p;   // b2 added once per node in the reduce kernel
        }
    }

    if (lane == 0) warp_sums[warp] = wsum;
    __syncthreads();

    if (tid == 0) {
        float s = 0.0f;
        #pragma unroll
        for (int w = 0; w < WARPS; ++w) s += warp_sums[w];
        g_partial[b * SPLIT + chunk] = s;
    }
}

__global__ void gcn_reduce(const float* __restrict__ b2, float* __restrict__ out)
{
    const int i = threadIdx.x;         // 256 threads = 256 batches
    float s = (float)Nn * b2[0];       // + b2 per node, summed over N nodes
    #pragma unroll
    for (int k = 0; k < SPLIT; ++k) s += g_partial[i * SPLIT + k];
    out[i] = s;
}

extern "C" void kernel_launch(void* const* d_in, const int* in_sizes, int n_in,
                              void* d_out, int out_size)
{
    const float* x   = (const float*)d_in[0];  // node_features [256,512,2]
    const float* adj = (const float*)d_in[1];  // adj_matrices  [256,512,512]
    const float* W1  = (const float*)d_in[2];  // [2,4]
    const float* b1  = (const float*)d_in[3];  // [4]
    const float* W2  = (const float*)d_in[4];  // [4,1]
    const float* b2  = (const float*)d_in[5];  // [1]
    float* out = (float*)d_out;                // [256,1]

    gcn_main<<<Bc * SPLIT, THREADS>>>(x, adj, W1, b1, W2);
    gcn_reduce<<<1, Bc>>>(b2, out);
}

// round 5
// speedup vs baseline: 1.1382x; 1.1382x over previous
#include <cuda_runtime.h>
#include <cuda_bf16.h>

static constexpr int Bc      = 256;          // batches
static constexpr int Nn      = 512;          // nodes
static constexpr int SPLIT   = 4;            // row-chunks per batch
static constexpr int ROWS    = Nn / SPLIT;   // 128 rows per block
static constexpr int THREADS = 256;
static constexpr int WARPS   = THREADS / 32;

// Deterministic partial sums: [batch][chunk]  (no FP atomics anywhere)
__device__ float g_partial[Bc * SPLIT];
// Per-batch completion counters (zero-init on module load; self-reset each run)
__device__ int   g_count[Bc];

__global__ __launch_bounds__(THREADS)
void gcn_fused(const float* __restrict__ x,     // [B, N, 2]
               const float* __restrict__ adj,   // [B, N, N]
               const float* __restrict__ W1,    // [2, 4] row-major
               const float* __restrict__ b1,    // [4]
               const float* __restrict__ W2,    // [4, 1]
               const float* __restrict__ b2,    // [1]
               float* __restrict__ out)         // [B, 1]
{
    const int blk   = blockIdx.x;
    const int b     = blk >> 2;                // / SPLIT
    const int chunk = blk & (SPLIT - 1);
    const int tid   = threadIdx.x;
    const int lane  = tid & 31;
    const int warp  = tid >> 5;

    __shared__ float sW[16];                   // [0..7]=W1, [8..11]=b1, [12..15]=W2
    __shared__ float warp_sums[WARPS];
    if (tid < 8)  sW[tid]      = W1[tid];
    if (tid < 4)  sW[8 + tid]  = b1[tid];
    if (tid < 4)  sW[12 + tid] = W2[tid];

    // Lane l owns columns m = it*128 + 4*l + k (it=0..3, k=0..3): fixed x-slice in regs.
    float rx0[16], rx1[16];
    {
        const float* xb = x + (size_t)b * Nn * 2;
        #pragma unroll
        for (int it = 0; it < 4; ++it) {
            const int m = it * 128 + lane * 4;
            #pragma unroll
            for (int k = 0; k < 4; ++k) {
                const float2 v = *(const float2*)(xb + (size_t)(m + k) * 2);
                rx0[it * 4 + k] = v.x;
                rx1[it * 4 + k] = v.y;
            }
        }
    }
    __syncthreads();

    float wsum = 0.0f;
    const int n_base = chunk * ROWS;

    // 2 consecutive rows per warp iteration: 8 front-batched float4 streaming
    // loads (4 KB contiguous) -> high MLP, shuffle tails of both rows overlap.
    for (int r = warp * 2; r < ROWS; r += WARPS * 2) {
        const float4* __restrict__ arow0 =
            (const float4*)(adj + ((size_t)b * Nn + n_base + r) * Nn);
        const float4* __restrict__ arow1 =
            (const float4*)(adj + ((size_t)b * Nn + n_base + r + 1) * Nn);

        float4 va[4], vb[4];
        #pragma unroll
        for (int it = 0; it < 4; ++it) va[it] = __ldcs(arow0 + it * 32 + lane);
        #pragma unroll
        for (int it = 0; it < 4; ++it) vb[it] = __ldcs(arow1 + it * 32 + lane);

        float s0a = 0.f, s1a = 0.f, s0b = 0.f, s1b = 0.f;
        #pragma unroll
        for (int it = 0; it < 4; ++it) {
            s0a = fmaf(va[it].x, rx0[it*4+0], s0a);  s1a = fmaf(va[it].x, rx1[it*4+0], s1a);
            s0a = fmaf(va[it].y, rx0[it*4+1], s0a);  s1a = fmaf(va[it].y, rx1[it*4+1], s1a);
            s0a = fmaf(va[it].z, rx0[it*4+2], s0a);  s1a = fmaf(va[it].z, rx1[it*4+2], s1a);
            s0a = fmaf(va[it].w, rx0[it*4+3], s0a);  s1a = fmaf(va[it].w, rx1[it*4+3], s1a);
            s0b = fmaf(vb[it].x, rx0[it*4+0], s0b);  s1b = fmaf(vb[it].x, rx1[it*4+0], s1b);
            s0b = fmaf(vb[it].y, rx0[it*4+1], s0b);  s1b = fmaf(vb[it].y, rx1[it*4+1], s1b);
            s0b = fmaf(vb[it].z, rx0[it*4+2], s0b);  s1b = fmaf(vb[it].z, rx1[it*4+2], s1b);
            s0b = fmaf(vb[it].w, rx0[it*4+3], s0b);  s1b = fmaf(vb[it].w, rx1[it*4+3], s1b);
        }

        #pragma unroll
        for (int off = 16; off > 0; off >>= 1) {
            s0a += __shfl_xor_sync(0xFFFFFFFFu, s0a, off);
            s1a += __shfl_xor_sync(0xFFFFFFFFu, s1a, off);
            s0b += __shfl_xor_sync(0xFFFFFFFFu, s0b, off);
            s1b += __shfl_xor_sync(0xFFFFFFFFu, s1b, off);
        }

        if (lane == 0) {
            float pa = 0.f, pb = 0.f;
            #pragma unroll
            for (int j = 0; j < 4; ++j) {
                const float ha = fmaf(s0a, sW[j], fmaf(s1a, sW[4 + j], sW[8 + j]));
                const float hb = fmaf(s0b, sW[j], fmaf(s1b, sW[4 + j], sW[8 + j]));
                pa = fmaf(fmaxf(ha, 0.0f), sW[12 + j], pa);
                pb = fmaf(fmaxf(hb, 0.0f), sW[12 + j], pb);
            }
            wsum += pa + pb;   // b2 added per-node at the end
        }
    }

    if (lane == 0) warp_sums[warp] = wsum;
    __syncthreads();

    if (tid == 0) {
        float s = 0.0f;
        #pragma unroll
        for (int w = 0; w < WARPS; ++w) s += warp_sums[w];
        g_partial[b * SPLIT + chunk] = s;

        // last-block-finishes: int atomic only; FP adds in fixed index order.
        __threadfence();
        const int old = atomicAdd(&g_count[b], 1);
        if (old == SPLIT - 1) {
            float tot = (float)Nn * __ldcg(b2);   // + b2 per node over N nodes
            #pragma unroll
            for (int k = 0; k < SPLIT; ++k)
                tot += __ldcg(&g_partial[b * SPLIT + k]);
            out[b] = tot;
            g_count[b] = 0;                       // reset for next replay
        }
    }
}

extern "C" void kernel_launch(void* const* d_in, const int* in_sizes, int n_in,
                              void* d_out, int out_size)
{
    const float* x   = (const float*)d_in[0];  // node_features [256,512,2]
    const float* adj = (const float*)d_in[1];  // adj_matrices  [256,512,512]
    const float* W1  = (const float*)d_in[2];  // [2,4]
    const float* b1  = (const float*)d_in[3];  // [4]
    const float* W2  = (const float*)d_in[4];  // [4,1]
    const float* b2  = (const float*)d_in[5];  // [1]
    float* out = (float*)d_out;                // [256,1]

    gcn_fused<<<Bc * SPLIT, THREADS>>>(x, adj, W1, b1, W2, b2, out);
}